// round 16
// baseline (speedup 1.0000x reference)
#include <cuda_runtime.h>
#include <math.h>
#include <stdint.h>

#define BATCH 2
#define SEQL  2048
#define EMB   1024
#define NH    16
#define HD    64
#define M1    (BATCH*SEQL)   // 4096
#define NQKV  (3*EMB)        // 3072

__device__ float g_q[BATCH*NH*SEQL*HD];   // [B,H,S,D] tf32, pre-scaled
__device__ float g_k[BATCH*NH*SEQL*HD];   // tf32
__device__ float g_v[BATCH*NH*SEQL*HD];   // tf32
__device__ float g_attn[M1 * EMB];        // [B,S,E]
__device__ float2 g_rope[SEQL * 32];      // (cos, sin) per (s, j)

__device__ __forceinline__ float cvt_tf32(float x) {
    uint32_t u;
    asm("cvt.rna.tf32.f32 %0, %1;" : "=r"(u) : "f"(x));
    return __uint_as_float(u);
}
__device__ __forceinline__ float ex2(float x) {
    float y;
    asm("ex2.approx.ftz.f32 %0, %1;" : "=f"(y) : "f"(x));
    return y;
}

__device__ __forceinline__ void mma8(float4& d, const float4& a, float b0, float b1) {
    asm volatile(
        "mma.sync.aligned.m16n8k8.row.col.f32.tf32.tf32.f32 "
        "{%0,%1,%2,%3}, {%4,%5,%6,%7}, {%8,%9}, {%0,%1,%2,%3};"
        : "+f"(d.x), "+f"(d.y), "+f"(d.z), "+f"(d.w)
        : "r"(__float_as_uint(a.x)), "r"(__float_as_uint(a.y)),
          "r"(__float_as_uint(a.z)), "r"(__float_as_uint(a.w)),
          "r"(__float_as_uint(b0)),  "r"(__float_as_uint(b1)));
}

__device__ __forceinline__ int swsl(int slot) { return slot ^ ((slot >> 3) & 3); }

// --- GEMM BK=32 layouts (tile stride 132, swizzled slots) ---
// A frag element (m, k<32): tile = (m>>4)*4 + (k>>3)
__device__ __forceinline__ int as32_idx(int m, int k) {
    int slot = ((m & 7) << 2) + (k & 3);
    return (((m >> 4) << 2) + (k >> 3)) * 132 + (swsl(slot) << 2)
         + (((k >> 2) & 1) << 1) + ((m >> 3) & 1);
}
// B frag element (n, k<32): tile = (k>>4)*16 + (n>>3)
__device__ __forceinline__ int bs32_idx(int n, int k) {
    int slot = ((n & 7) << 2) + (k & 3);
    return (((k >> 4) << 4) + (n >> 3)) * 132 + (swsl(slot) << 2)
         + (((k >> 3) & 1) << 1) + ((k >> 2) & 1);
}
// --- Flash layouts (validated) ---
__device__ __forceinline__ int kf_idx(int d, int key) {
    int slot = ((key & 7) << 2) + (d & 3);
    return (((key >> 3) << 2) + (d >> 4)) * 132 + (swsl(slot) << 2)
         + (((d >> 3) & 1) << 1) + ((d >> 2) & 1);
}
__device__ __forceinline__ int vf_idx(int key, int d) {
    int slot = ((d & 7) << 2) + (key & 3);
    return (((key >> 4) << 3) + (d >> 3)) * 132 + (swsl(slot) << 2)
         + (((key >> 3) & 1) << 1) + ((key >> 2) & 1);
}
__device__ __forceinline__ int qf_idx(int m, int d) {
    int slot = ((m & 7) << 2) + (d & 3);
    return (d >> 3) * 132 + (swsl(slot) << 2)
         + (((d >> 2) & 1) << 1) + ((m >> 3) & 1);
}
__device__ __forceinline__ int vperm(int key) {
    int r = key & 7;
    int j = (r & 1) ? (4 + (r >> 1)) : (r >> 1);
    return (key & ~7) | j;
}
__device__ __forceinline__ float4 apfrag(const float4& S) {
    return make_float4(cvt_tf32(S.x), cvt_tf32(S.z), cvt_tf32(S.y), cvt_tf32(S.w));
}

__global__ void dummy_k() {}

// ---------------------------------------------------------------------------
// rope table init
// ---------------------------------------------------------------------------
__global__ __launch_bounds__(256) void rope_init(float2* __restrict__ tab)
{
    int idx = blockIdx.x * blockDim.x + threadIdx.x;
    int j = idx & 31;
    int s = idx >> 5;
    float inv = expf((float)j * -0.28782313662425575f);
    float sn, cs;
    sincosf((float)s * inv, &sn, &cs);
    tab[idx] = make_float2(cs, sn);
}

// ---------------------------------------------------------------------------
// Dense GEMM, BK=32: 128x128 block tile, 4 warps x (64x64), 2 CTAs/SM,
// 128 HMMA per warp between syncs (flash parity); dynamic smem 67.6 KB.
// mode=1: fused RoPE/split epilogue (table trig) writing q/k/v [B,H,S,D].
// ---------------------------------------------------------------------------
#define GEMM_SMEM_FLOATS (4 * 4224)     // As0,As1,Bs0,Bs1
__global__ __launch_bounds__(128, 2) void gemm_tf32(
    const float* __restrict__ A, const float* __restrict__ Bm,
    float* __restrict__ C, int M, int N, int K, int mode,
    float* __restrict__ qout, float* __restrict__ kout, float* __restrict__ vout,
    const float2* __restrict__ rope)
{
    extern __shared__ float gsm[];
    float* AsS[2] = { gsm,            gsm + 4224 };
    float* BsS[2] = { gsm + 2 * 4224, gsm + 3 * 4224 };

    const int tid  = threadIdx.x;
    const int lane = tid & 31;
    const int warp = tid >> 5;      // 0..3
    const int wm = warp >> 1;
    const int wn = warp & 1;
    const int m0 = blockIdx.y << 7;
    const int n0 = blockIdx.x << 7;
    const int g = lane >> 2, tig = lane & 3;
    const int sw4 = swsl(lane) << 2;

    const int rA  = tid >> 2;          // 0..31
    const int kk4 = (tid & 3) << 2;    // 0,4,8,12

    int aoff[4], boff[4];
#pragma unroll
    for (int u = 0; u < 4; u++) {
        aoff[u] = as32_idx(rA, kk4 + u);   // second k-half: +264
        boff[u] = bs32_idx(rA, kk4 + u);   // second k-half: +2112
    }

    const float* Aptr = A  + (size_t)m0 * K;
    const float* Bptr = Bm + (size_t)n0 * K;

    float4 acc[4][8];
#pragma unroll
    for (int i = 0; i < 4; i++)
#pragma unroll
        for (int j = 0; j < 8; j++) acc[i][j] = make_float4(0.f,0.f,0.f,0.f);

    float4 pa[8], pb[8];   // [blk*2 + khalf]

#define G_LDG(KOFS)                                                           \
    {                                                                         \
        _Pragma("unroll")                                                     \
        for (int blk = 0; blk < 4; blk++) {                                   \
            pa[blk*2+0] = *(const float4*)&Aptr[(size_t)(rA + 32*blk) * K + (KOFS) + kk4];      \
            pa[blk*2+1] = *(const float4*)&Aptr[(size_t)(rA + 32*blk) * K + (KOFS) + kk4 + 16]; \
            pb[blk*2+0] = *(const float4*)&Bptr[(size_t)(rA + 32*blk) * K + (KOFS) + kk4];      \
            pb[blk*2+1] = *(const float4*)&Bptr[(size_t)(rA + 32*blk) * K + (KOFS) + kk4 + 16]; \
        }                                                                     \
    }

#define G_STS(ST)                                                             \
    {                                                                         \
        float* Ad = AsS[ST];                                                  \
        float* Bd = BsS[ST];                                                  \
        _Pragma("unroll")                                                     \
        for (int blk = 0; blk < 4; blk++) {                                   \
            Ad[aoff[0] + blk*1056]       = cvt_tf32(pa[blk*2+0].x);           \
            Ad[aoff[1] + blk*1056]       = cvt_tf32(pa[blk*2+0].y);           \
            Ad[aoff[2] + blk*1056]       = cvt_tf32(pa[blk*2+0].z);           \
            Ad[aoff[3] + blk*1056]       = cvt_tf32(pa[blk*2+0].w);           \
            Ad[aoff[0] + blk*1056 + 264] = cvt_tf32(pa[blk*2+1].x);           \
            Ad[aoff[1] + blk*1056 + 264] = cvt_tf32(pa[blk*2+1].y);           \
            Ad[aoff[2] + blk*1056 + 264] = cvt_tf32(pa[blk*2+1].z);           \
            Ad[aoff[3] + blk*1056 + 264] = cvt_tf32(pa[blk*2+1].w);           \
            Bd[boff[0] + blk*528]        = cvt_tf32(pb[blk*2+0].x);           \
            Bd[boff[1] + blk*528]        = cvt_tf32(pb[blk*2+0].y);           \
            Bd[boff[2] + blk*528]        = cvt_tf32(pb[blk*2+0].z);           \
            Bd[boff[3] + blk*528]        = cvt_tf32(pb[blk*2+0].w);           \
            Bd[boff[0] + blk*528 + 2112] = cvt_tf32(pb[blk*2+1].x);           \
            Bd[boff[1] + blk*528 + 2112] = cvt_tf32(pb[blk*2+1].y);           \
            Bd[boff[2] + blk*528 + 2112] = cvt_tf32(pb[blk*2+1].z);           \
            Bd[boff[3] + blk*528 + 2112] = cvt_tf32(pb[blk*2+1].w);           \
        }                                                                     \
    }

    // prologue: chunk 0 -> stage 0
    G_LDG(0);
    G_STS(0);
    __syncthreads();

    const int NK = K >> 5;   // BK=32 chunks
    for (int kt = 0; kt < NK; kt++) {
        const int st = kt & 1;
        if (kt + 1 < NK) G_LDG((kt + 1) << 5);

        const float* Asb = AsS[st];
        const float* Bsb = BsS[st];
#pragma unroll
        for (int kg = 0; kg < 2; kg++) {            // two k16 groups
#pragma unroll
            for (int ng = 0; ng < 2; ng++) {
                float4 b4[4];
#pragma unroll
                for (int j = 0; j < 4; j++)
                    b4[j] = *(const float4*)&Bsb[(kg*16 + wn*8 + ng*4 + j) * 132 + sw4];
#pragma unroll
                for (int k8 = 0; k8 < 2; k8++) {
                    float4 a4[4];
#pragma unroll
                    for (int mt = 0; mt < 4; mt++)
                        a4[mt] = *(const float4*)&Asb[((wm*4+mt)*4 + kg*2 + k8) * 132 + sw4];
#pragma unroll
                    for (int mt = 0; mt < 4; mt++)
#pragma unroll
                        for (int j = 0; j < 4; j++) {
                            if (k8 == 0) mma8(acc[mt][ng*4+j], a4[mt], b4[j].x, b4[j].y);
                            else         mma8(acc[mt][ng*4+j], a4[mt], b4[j].z, b4[j].w);
                        }
                }
            }
        }

        if (kt + 1 < NK) {
            const int s2 = (kt + 1) & 1;
            G_STS(s2);
        }
        __syncthreads();
    }
#undef G_LDG
#undef G_STS

    if (mode == 0) {
#pragma unroll
        for (int mt = 0; mt < 4; mt++) {
            int mrow = m0 + wm * 64 + mt * 16 + g;
#pragma unroll
            for (int nt = 0; nt < 8; nt++) {
                int ncol = n0 + wn * 64 + nt * 8 + tig * 2;
                *(float2*)&C[(size_t)mrow * N + ncol]       = make_float2(acc[mt][nt].x, acc[mt][nt].y);
                *(float2*)&C[(size_t)(mrow + 8) * N + ncol] = make_float2(acc[mt][nt].z, acc[mt][nt].w);
            }
        }
        return;
    }

    // --- fused RoPE/split epilogue (mode 1), table-based trig ---
    const int col0 = n0 + wn * 64;
    const int sec  = col0 >> 10;         // 0=q, 1=k, 2=v
    const int hh   = (col0 & 1023) >> 6;
    float* outp = (sec == 0) ? qout : (sec == 1 ? kout : vout);
    const float QS = 0.18033688011112042f;
    const float scl = (sec == 0) ? QS : 1.0f;

#pragma unroll
    for (int mt = 0; mt < 4; mt++) {
        int mrow = m0 + wm * 64 + mt * 16 + g;
        int b_ = mrow >> 11, s_ = mrow & 2047;
        size_t base0 = ((size_t)(b_ * NH + hh) * SEQL + s_) * HD;
        size_t base1 = base0 + 8 * (size_t)HD;
#pragma unroll
        for (int nt = 0; nt < 4; nt++) {
            int j0 = nt * 8 + tig * 2;
            if (sec == 2) {
                *(float2*)&outp[base0 + j0] =
                    make_float2(cvt_tf32(acc[mt][nt].x), cvt_tf32(acc[mt][nt].y));
                *(float2*)&outp[base0 + j0 + 32] =
                    make_float2(cvt_tf32(acc[mt][nt+4].x), cvt_tf32(acc[mt][nt+4].y));
                *(float2*)&outp[base1 + j0] =
                    make_float2(cvt_tf32(acc[mt][nt].z), cvt_tf32(acc[mt][nt].w));
                *(float2*)&outp[base1 + j0 + 32] =
                    make_float2(cvt_tf32(acc[mt][nt+4].z), cvt_tf32(acc[mt][nt+4].w));
            } else {
                float2 tA0 = rope[s_ * 32 + j0];
                float2 tB0 = rope[s_ * 32 + j0 + 1];
                float2 tA1 = rope[(s_ + 8) * 32 + j0];
                float2 tB1 = rope[(s_ + 8) * 32 + j0 + 1];

                float x1 = acc[mt][nt].x,   y1 = acc[mt][nt].y;
                float x2 = acc[mt][nt+4].x, y2 = acc[mt][nt+4].y;
                *(float2*)&outp[base0 + j0] = make_float2(
                    cvt_tf32(scl * (x1 * tA0.x - x2 * tA0.y)),
                    cvt_tf32(scl * (y1 * tB0.x - y2 * tB0.y)));
                *(float2*)&outp[base0 + j0 + 32] = make_float2(
                    cvt_tf32(scl * (x2 * tA0.x + x1 * tA0.y)),
                    cvt_tf32(scl * (y2 * tB0.x + y1 * tB0.y)));
                float z1 = acc[mt][nt].z,   w1 = acc[mt][nt].w;
                float z2 = acc[mt][nt+4].z, w2 = acc[mt][nt+4].w;
                *(float2*)&outp[base1 + j0] = make_float2(
                    cvt_tf32(scl * (z1 * tA1.x - z2 * tA1.y)),
                    cvt_tf32(scl * (w1 * tB1.x - w2 * tB1.y)));
                *(float2*)&outp[base1 + j0 + 32] = make_float2(
                    cvt_tf32(scl * (z2 * tA1.x + z1 * tA1.y)),
                    cvt_tf32(scl * (w2 * tB1.x + w1 * tB1.y)));
            }
        }
    }
}

// ---------------------------------------------------------------------------
// Flash attention, m32 warp tiles (unchanged R15 body).
// ---------------------------------------------------------------------------
__global__ __launch_bounds__(128, 2) void flash_tf32(
    const float* __restrict__ Qg, const float* __restrict__ Kg,
    const float* __restrict__ Vg, const unsigned char* __restrict__ maskg,
    float* __restrict__ Out)
{
    extern __shared__ float sm[];
    float* Qf = sm;                 // 8448
    float* Kb = sm + 8448;          // 2 x 4224
    float* Vb = sm + 16896;         // 2 x 4224
    float* mk = sm + 25344;         // 2048

    const int tid = threadIdx.x, lane = tid & 31, warp = tid >> 5;
    const int g = lane >> 2, tig = lane & 3;
    const int sw4 = swsl(lane) << 2;
    const int q0 = blockIdx.x << 7;
    const int h  = blockIdx.y;
    const int b  = blockIdx.z;
    const size_t bh = (size_t)(b * NH + h) * SEQL * HD;

    const float* kbase = Kg + bh;
    const float* vbase = Vg + bh;

    const int cst = tid >> 4;
    const int csd = (tid & 15) << 2;

    int koff[4], voff[4];
#pragma unroll
    for (int u = 0; u < 4; u++) {
        koff[u] = kf_idx(csd + u, cst);
        voff[u] = vf_idx(vperm(cst), csd + u);
    }

    {
        const float* qp = Qg + bh + (size_t)q0 * HD;
#pragma unroll
        for (int jj = 0; jj < 16; jj++) {
            int c = tid + jj * 128;
            int row = c >> 4;
            int d4  = (c & 15) << 2;
            float4 qv = *(const float4*)&qp[(size_t)row * HD + d4];
            int w = row >> 4, m = row & 15;
#pragma unroll
            for (int u = 0; u < 4; u++)
                Qf[w * 1056 + qf_idx(m, d4 + u)] = ((const float*)&qv)[u];
        }
#pragma unroll
        for (int jj = 0; jj < 16; jj++) {
            int i = tid + jj * 128;
            mk[i] = maskg[b * SEQL + i] ? -1.0e9f : 0.0f;
        }
    }

    {
#pragma unroll
        for (int jj = 0; jj < 8; jj++) {
            int key = cst + jj * 8;
            float4 kv = *(const float4*)&kbase[(size_t)key * HD + csd];
            float4 vv = *(const float4*)&vbase[(size_t)key * HD + csd];
#pragma unroll
            for (int u = 0; u < 4; u++) {
                Kb[koff[u] + jj * 528] = ((const float*)&kv)[u];
                Vb[voff[u] + (jj >> 1) * 1056 + (jj & 1) * 2] = ((const float*)&vv)[u];
            }
        }
    }
    __syncthreads();

    float4 O[2][8];
#pragma unroll
    for (int mt = 0; mt < 2; mt++)
#pragma unroll
        for (int nt = 0; nt < 8; nt++) O[mt][nt] = make_float4(0.f,0.f,0.f,0.f);
    float l0 = 0.f, l1 = 0.f, l2 = 0.f, l3 = 0.f;

    for (int t = 0; t < SEQL / 64; t++) {
        const int buf = (t & 1) * 4224;
        const bool more = (t + 1 < SEQL / 64);

        float4 pk[8];
        if (more) {
#pragma unroll
            for (int jj = 0; jj < 8; jj++)
                pk[jj] = *(const float4*)&kbase[(size_t)((t+1)*64 + cst + jj*8) * HD + csd];
        }

        float4 S[2][8];
#pragma unroll
        for (int nt = 0; nt < 8; nt++) {
            float2 mv = *(const float2*)&mk[t * 64 + nt * 8 + tig * 2];
            S[0][nt] = make_float4(mv.x, mv.y, mv.x, mv.y);
            S[1][nt] = S[0][nt];
        }

        const float* Kf = Kb + buf;
        const float* Q0 = Qf + (2 * warp)     * 1056;
        const float* Q1 = Qf + (2 * warp + 1) * 1056;
#pragma unroll
        for (int k8p = 0; k8p < 4; k8p++) {
            float4 qa0 = *(const float4*)&Q0[(2 * k8p)     * 132 + sw4];
            float4 qb0 = *(const float4*)&Q0[(2 * k8p + 1) * 132 + sw4];
            float4 qa1 = *(const float4*)&Q1[(2 * k8p)     * 132 + sw4];
            float4 qb1 = *(const float4*)&Q1[(2 * k8p + 1) * 132 + sw4];
#pragma unroll
            for (int ng = 0; ng < 2; ng++) {
                float4 bq[4];
#pragma unroll
                for (int j = 0; j < 4; j++)
                    bq[j] = *(const float4*)&Kf[((ng * 4 + j) * 4 + k8p) * 132 + sw4];
#pragma unroll
                for (int j = 0; j < 4; j++) mma8(S[0][ng*4+j], qa0, bq[j].x, bq[j].y);
#pragma unroll
                for (int j = 0; j < 4; j++) mma8(S[1][ng*4+j], qa1, bq[j].x, bq[j].y);
#pragma unroll
                for (int j = 0; j < 4; j++) mma8(S[0][ng*4+j], qb0, bq[j].z, bq[j].w);
#pragma unroll
                for (int j = 0; j < 4; j++) mma8(S[1][ng*4+j], qb1, bq[j].z, bq[j].w);
            }
        }

        if (more) {
            float* Kn = Kb + (buf ^ 4224);
#pragma unroll
            for (int jj = 0; jj < 8; jj++)
#pragma unroll
                for (int u = 0; u < 4; u++)
                    Kn[koff[u] + jj * 528] = ((const float*)&pk[jj])[u];
        }

        float4 pv4[8];
        if (more) {
#pragma unroll
            for (int jj = 0; jj < 8; jj++)
                pv4[jj] = *(const float4*)&vbase[(size_t)((t+1)*64 + cst + jj*8) * HD + csd];
        }

#pragma unroll
        for (int nt = 0; nt < 8; nt++) {
            S[0][nt].x = ex2(S[0][nt].x); S[0][nt].y = ex2(S[0][nt].y);
            S[0][nt].z = ex2(S[0][nt].z); S[0][nt].w = ex2(S[0][nt].w);
            l0 += S[0][nt].x + S[0][nt].y;
            l1 += S[0][nt].z + S[0][nt].w;
            S[1][nt].x = ex2(S[1][nt].x); S[1][nt].y = ex2(S[1][nt].y);
            S[1][nt].z = ex2(S[1][nt].z); S[1][nt].w = ex2(S[1][nt].w);
            l2 += S[1][nt].x + S[1][nt].y;
            l3 += S[1][nt].z + S[1][nt].w;
        }

        const float* Vf = Vb + buf;
#pragma unroll
        for (int kp = 0; kp < 4; kp++) {
            float4 ape0 = apfrag(S[0][2*kp]);
            float4 apo0 = apfrag(S[0][2*kp+1]);
            float4 ape1 = apfrag(S[1][2*kp]);
            float4 apo1 = apfrag(S[1][2*kp+1]);
#pragma unroll
            for (int ng = 0; ng < 2; ng++) {
                float4 bv[4];
#pragma unroll
                for (int j = 0; j < 4; j++)
                    bv[j] = *(const float4*)&Vf[(kp * 8 + ng * 4 + j) * 132 + sw4];
#pragma unroll
                for (int j = 0; j < 4; j++) mma8(O[0][ng*4+j], ape0, bv[j].x, bv[j].y);
#pragma unroll
                for (int j = 0; j < 4; j++) mma8(O[1][ng*4+j], ape1, bv[j].x, bv[j].y);
#pragma unroll
                for (int j = 0; j < 4; j++) mma8(O[0][ng*4+j], apo0, bv[j].z, bv[j].w);
#pragma unroll
                for (int j = 0; j < 4; j++) mma8(O[1][ng*4+j], apo1, bv[j].z, bv[j].w);
            }
        }

        if (more) {
            float* Vn = Vb + (buf ^ 4224);
#pragma unroll
            for (int jj = 0; jj < 8; jj++)
#pragma unroll
                for (int u = 0; u < 4; u++)
                    Vn[voff[u] + (jj >> 1) * 1056 + (jj & 1) * 2] = ((const float*)&pv4[jj])[u];
        }
        __syncthreads();
    }

    l0 += __shfl_xor_sync(0xffffffffu, l0, 1);
    l0 += __shfl_xor_sync(0xffffffffu, l0, 2);
    l1 += __shfl_xor_sync(0xffffffffu, l1, 1);
    l1 += __shfl_xor_sync(0xffffffffu, l1, 2);
    l2 += __shfl_xor_sync(0xffffffffu, l2, 1);
    l2 += __shfl_xor_sync(0xffffffffu, l2, 2);
    l3 += __shfl_xor_sync(0xffffffffu, l3, 1);
    l3 += __shfl_xor_sync(0xffffffffu, l3, 2);
    float inv_[4] = {1.f / l0, 1.f / l1, 1.f / l2, 1.f / l3};
#pragma unroll
    for (int mt = 0; mt < 2; mt++) {
        int s0 = q0 + (2 * warp + mt) * 16 + g;
        float iv0 = inv_[2 * mt], iv1 = inv_[2 * mt + 1];
#pragma unroll
        for (int nt = 0; nt < 8; nt++) {
            int col = h * HD + nt * 8 + tig * 2;
            *(float2*)&Out[(size_t)(b * SEQL + s0) * EMB + col] =
                make_float2(O[mt][nt].x * iv0, O[mt][nt].y * iv0);
            *(float2*)&Out[(size_t)(b * SEQL + s0 + 8) * EMB + col] =
                make_float2(O[mt][nt].z * iv1, O[mt][nt].w * iv1);
        }
    }
}

// ---------------------------------------------------------------------------
extern "C" void kernel_launch(void* const* d_in, const int* in_sizes, int n_in,
                              void* d_out, int out_size)
{
    const float* x            = (const float*)d_in[0];
    const unsigned char* mask = (const unsigned char*)d_in[1];
    const float* Wqkv         = (const float*)d_in[2];
    const float* Wout         = (const float*)d_in[3];
    float* out = (float*)d_out;

    float *q, *k, *v, *attn;
    float2* rope;
    cudaGetSymbolAddress((void**)&q,    g_q);
    cudaGetSymbolAddress((void**)&k,    g_k);
    cudaGetSymbolAddress((void**)&v,    g_v);
    cudaGetSymbolAddress((void**)&attn, g_attn);
    cudaGetSymbolAddress((void**)&rope, g_rope);

    const int FLASH_SMEM = 27392 * 4;              // 109568 B
    const int GEMM_SMEM  = GEMM_SMEM_FLOATS * 4;   // 67584 B
    cudaFuncSetAttribute(flash_tf32,
                         cudaFuncAttributeMaxDynamicSharedMemorySize, FLASH_SMEM);
    cudaFuncSetAttribute(gemm_tf32,
                         cudaFuncAttributeMaxDynamicSharedMemorySize, GEMM_SMEM);

    rope_init<<<(SEQL * 32) / 256, 256>>>(rope);

    // keep ncu -s 5 -c 1 window on gemm1 (grid=768)
    dummy_k<<<1, 32>>>();
    dummy_k<<<1, 32>>>();

    dim3 g1(NQKV / 128, M1 / 128);
    gemm_tf32<<<g1, 128, GEMM_SMEM>>>(x, Wqkv, nullptr, M1, NQKV, EMB, 1,
                                      q, k, v, rope);

    dim3 gf(SEQL / 128, NH, BATCH);
    flash_tf32<<<gf, 128, FLASH_SMEM>>>(q, k, v, mask, attn);

    dim3 g2(EMB / 128, M1 / 128);
    gemm_tf32<<<g2, 128, GEMM_SMEM>>>(attn, Wout, out, M1, EMB, EMB, 0,
                                      nullptr, nullptr, nullptr, nullptr);
}

// round 17
// speedup vs baseline: 1.1218x; 1.1218x over previous
#include <cuda_runtime.h>
#include <math.h>
#include <stdint.h>

#define BATCH 2
#define SEQL  2048
#define EMB   1024
#define NH    16
#define HD    64
#define M1    (BATCH*SEQL)   // 4096
#define NQKV  (3*EMB)        // 3072

__device__ float g_q[BATCH*NH*SEQL*HD];   // [B,H,S,D] tf32, pre-scaled
__device__ float g_k[BATCH*NH*SEQL*HD];   // tf32
__device__ float g_v[BATCH*NH*SEQL*HD];   // tf32
__device__ float g_attn[M1 * EMB];        // [B,S,E]
__device__ float2 g_rope[SEQL * 32];      // (cos, sin) per (s, j)

__device__ __forceinline__ float cvt_tf32(float x) {
    uint32_t u;
    asm("cvt.rna.tf32.f32 %0, %1;" : "=r"(u) : "f"(x));
    return __uint_as_float(u);
}
__device__ __forceinline__ float ex2(float x) {
    float y;
    asm("ex2.approx.ftz.f32 %0, %1;" : "=f"(y) : "f"(x));
    return y;
}

__device__ __forceinline__ void mma8(float4& d, const float4& a, float b0, float b1) {
    asm volatile(
        "mma.sync.aligned.m16n8k8.row.col.f32.tf32.tf32.f32 "
        "{%0,%1,%2,%3}, {%4,%5,%6,%7}, {%8,%9}, {%0,%1,%2,%3};"
        : "+f"(d.x), "+f"(d.y), "+f"(d.z), "+f"(d.w)
        : "r"(__float_as_uint(a.x)), "r"(__float_as_uint(a.y)),
          "r"(__float_as_uint(a.z)), "r"(__float_as_uint(a.w)),
          "r"(__float_as_uint(b0)),  "r"(__float_as_uint(b1)));
}

__device__ __forceinline__ int swsl(int slot) { return slot ^ ((slot >> 3) & 3); }

// --- GEMM BK=16 layouts (tile stride 132, swizzled slots) ---
__device__ __forceinline__ int as_idx(int m, int k) {
    int slot = ((m & 7) << 2) + (k & 3);
    return (((m >> 4) << 1) + (k >> 3)) * 132 + (swsl(slot) << 2)
         + (((k >> 2) & 1) << 1) + ((m >> 3) & 1);
}
__device__ __forceinline__ int bs_idx(int n, int k) {
    int slot = ((n & 7) << 2) + (k & 3);
    return (n >> 3) * 132 + (swsl(slot) << 2)
         + (((k >> 3) & 1) << 1) + ((k >> 2) & 1);
}
// --- Flash layouts ---
__device__ __forceinline__ int kf_idx(int d, int key) {
    int slot = ((key & 7) << 2) + (d & 3);
    return (((key >> 3) << 2) + (d >> 4)) * 132 + (swsl(slot) << 2)
         + (((d >> 3) & 1) << 1) + ((d >> 2) & 1);
}
__device__ __forceinline__ int vf_idx(int key, int d) {
    int slot = ((d & 7) << 2) + (key & 3);
    return (((key >> 4) << 3) + (d >> 3)) * 132 + (swsl(slot) << 2)
         + (((key >> 3) & 1) << 1) + ((key >> 2) & 1);
}
__device__ __forceinline__ int qf_idx(int m, int d) {
    int slot = ((m & 7) << 2) + (d & 3);
    return (d >> 3) * 132 + (swsl(slot) << 2)
         + (((d >> 2) & 1) << 1) + ((m >> 3) & 1);
}
__device__ __forceinline__ int vperm(int key) {
    int r = key & 7;
    int j = (r & 1) ? (4 + (r >> 1)) : (r >> 1);
    return (key & ~7) | j;
}
__device__ __forceinline__ float4 apfrag(const float4& S) {
    return make_float4(cvt_tf32(S.x), cvt_tf32(S.z), cvt_tf32(S.y), cvt_tf32(S.w));
}

// ---------------------------------------------------------------------------
// rope table init
// ---------------------------------------------------------------------------
__global__ __launch_bounds__(256) void rope_init(float2* __restrict__ tab)
{
    int idx = blockIdx.x * blockDim.x + threadIdx.x;
    int j = idx & 31;
    int s = idx >> 5;
    float inv = expf((float)j * -0.28782313662425575f);
    float sn, cs;
    sincosf((float)s * inv, &sn, &cs);
    tab[idx] = make_float2(cs, sn);
}

// ---------------------------------------------------------------------------
// Dense GEMM (R15/R12 body): 128x128 block tile, BK=16, 4 warps x (64x64),
// 2 CTAs/SM, static smem double buffer. mode=0: plain C store.
// mode=1: fused RoPE/split epilogue (table trig) -> q/k/v [B,H,S,D] tf32.
// ---------------------------------------------------------------------------
__global__ __launch_bounds__(128, 2) void gemm_tf32(
    const float* __restrict__ A, const float* __restrict__ Bm,
    float* __restrict__ C, int M, int N, int K, int mode,
    float* __restrict__ qout, float* __restrict__ kout, float* __restrict__ vout,
    const float2* __restrict__ rope)
{
    __shared__ float As[2][2112];
    __shared__ float Bs[2][2112];

    const int tid  = threadIdx.x;
    const int lane = tid & 31;
    const int warp = tid >> 5;      // 0..3
    const int wm = warp >> 1;
    const int wn = warp & 1;
    const int m0 = blockIdx.y << 7;
    const int n0 = blockIdx.x << 7;
    const int g = lane >> 2, tig = lane & 3;
    const int sw4 = swsl(lane) << 2;

    const int rA  = tid >> 2;          // 0..31
    const int kkA = (tid & 3) << 2;    // 0,4,8,12

    int aoff[4], boff[4];
#pragma unroll
    for (int u = 0; u < 4; u++) {
        aoff[u] = as_idx(rA, kkA + u);
        boff[u] = bs_idx(rA, kkA + u);
    }

    const float* Aptr = A  + (size_t)m0 * K;
    const float* Bptr = Bm + (size_t)n0 * K;

    float4 acc[4][8];
#pragma unroll
    for (int i = 0; i < 4; i++)
#pragma unroll
        for (int j = 0; j < 8; j++) acc[i][j] = make_float4(0.f,0.f,0.f,0.f);

    float4 pa[4], pb[4];
#pragma unroll
    for (int blk = 0; blk < 4; blk++) {
        pa[blk] = *(const float4*)&Aptr[(size_t)(rA + 32*blk) * K + kkA];
        pb[blk] = *(const float4*)&Bptr[(size_t)(rA + 32*blk) * K + kkA];
    }
#pragma unroll
    for (int blk = 0; blk < 4; blk++)
#pragma unroll
        for (int u = 0; u < 4; u++) {
            As[0][aoff[u] + blk * 528] = cvt_tf32(((const float*)&pa[blk])[u]);
            Bs[0][boff[u] + blk * 528] = cvt_tf32(((const float*)&pb[blk])[u]);
        }
    __syncthreads();

    const int NK = K >> 4;
    for (int kt = 0; kt < NK; kt++) {
        const int st = kt & 1;
        if (kt + 1 < NK) {
            int k0 = (kt + 1) << 4;
#pragma unroll
            for (int blk = 0; blk < 4; blk++) {
                pa[blk] = *(const float4*)&Aptr[(size_t)(rA + 32*blk) * K + k0 + kkA];
                pb[blk] = *(const float4*)&Bptr[(size_t)(rA + 32*blk) * K + k0 + kkA];
            }
        }

#pragma unroll
        for (int ng = 0; ng < 2; ng++) {
            float4 b4[4];
#pragma unroll
            for (int j = 0; j < 4; j++)
                b4[j] = *(const float4*)&Bs[st][(wn * 8 + ng * 4 + j) * 132 + sw4];
#pragma unroll
            for (int k8 = 0; k8 < 2; k8++) {
                float4 a4[4];
#pragma unroll
                for (int mt = 0; mt < 4; mt++)
                    a4[mt] = *(const float4*)&As[st][((wm * 4 + mt) * 2 + k8) * 132 + sw4];
#pragma unroll
                for (int mt = 0; mt < 4; mt++)
#pragma unroll
                    for (int j = 0; j < 4; j++) {
                        if (k8 == 0) mma8(acc[mt][ng*4+j], a4[mt], b4[j].x, b4[j].y);
                        else         mma8(acc[mt][ng*4+j], a4[mt], b4[j].z, b4[j].w);
                    }
            }
        }

        if (kt + 1 < NK) {
            const int s2 = (kt + 1) & 1;
#pragma unroll
            for (int blk = 0; blk < 4; blk++)
#pragma unroll
                for (int u = 0; u < 4; u++) {
                    As[s2][aoff[u] + blk * 528] = cvt_tf32(((const float*)&pa[blk])[u]);
                    Bs[s2][boff[u] + blk * 528] = cvt_tf32(((const float*)&pb[blk])[u]);
                }
        }
        __syncthreads();
    }

    if (mode == 0) {
#pragma unroll
        for (int mt = 0; mt < 4; mt++) {
            int mrow = m0 + wm * 64 + mt * 16 + g;
#pragma unroll
            for (int nt = 0; nt < 8; nt++) {
                int ncol = n0 + wn * 64 + nt * 8 + tig * 2;
                *(float2*)&C[(size_t)mrow * N + ncol]       = make_float2(acc[mt][nt].x, acc[mt][nt].y);
                *(float2*)&C[(size_t)(mrow + 8) * N + ncol] = make_float2(acc[mt][nt].z, acc[mt][nt].w);
            }
        }
        return;
    }

    // --- fused RoPE/split epilogue (mode 1), table-based trig ---
    const int col0 = n0 + wn * 64;
    const int sec  = col0 >> 10;         // 0=q, 1=k, 2=v
    const int hh   = (col0 & 1023) >> 6;
    float* outp = (sec == 0) ? qout : (sec == 1 ? kout : vout);
    const float QS = 0.18033688011112042f;   // 0.125*log2(e)
    const float scl = (sec == 0) ? QS : 1.0f;

#pragma unroll
    for (int mt = 0; mt < 4; mt++) {
        int mrow = m0 + wm * 64 + mt * 16 + g;
        int b_ = mrow >> 11, s_ = mrow & 2047;
        size_t base0 = ((size_t)(b_ * NH + hh) * SEQL + s_) * HD;
        size_t base1 = base0 + 8 * (size_t)HD;
#pragma unroll
        for (int nt = 0; nt < 4; nt++) {
            int j0 = nt * 8 + tig * 2;
            if (sec == 2) {
                *(float2*)&outp[base0 + j0] =
                    make_float2(cvt_tf32(acc[mt][nt].x), cvt_tf32(acc[mt][nt].y));
                *(float2*)&outp[base0 + j0 + 32] =
                    make_float2(cvt_tf32(acc[mt][nt+4].x), cvt_tf32(acc[mt][nt+4].y));
                *(float2*)&outp[base1 + j0] =
                    make_float2(cvt_tf32(acc[mt][nt].z), cvt_tf32(acc[mt][nt].w));
                *(float2*)&outp[base1 + j0 + 32] =
                    make_float2(cvt_tf32(acc[mt][nt+4].z), cvt_tf32(acc[mt][nt+4].w));
            } else {
                float2 tA0 = rope[s_ * 32 + j0];
                float2 tB0 = rope[s_ * 32 + j0 + 1];
                float2 tA1 = rope[(s_ + 8) * 32 + j0];
                float2 tB1 = rope[(s_ + 8) * 32 + j0 + 1];

                float x1 = acc[mt][nt].x,   y1 = acc[mt][nt].y;
                float x2 = acc[mt][nt+4].x, y2 = acc[mt][nt+4].y;
                *(float2*)&outp[base0 + j0] = make_float2(
                    cvt_tf32(scl * (x1 * tA0.x - x2 * tA0.y)),
                    cvt_tf32(scl * (y1 * tB0.x - y2 * tB0.y)));
                *(float2*)&outp[base0 + j0 + 32] = make_float2(
                    cvt_tf32(scl * (x2 * tA0.x + x1 * tA0.y)),
                    cvt_tf32(scl * (y2 * tB0.x + y1 * tB0.y)));
                float z1 = acc[mt][nt].z,   w1 = acc[mt][nt].w;
                float z2 = acc[mt][nt+4].z, w2 = acc[mt][nt+4].w;
                *(float2*)&outp[base1 + j0] = make_float2(
                    cvt_tf32(scl * (z1 * tA1.x - z2 * tA1.y)),
                    cvt_tf32(scl * (w1 * tB1.x - w2 * tB1.y)));
                *(float2*)&outp[base1 + j0 + 32] = make_float2(
                    cvt_tf32(scl * (z2 * tA1.x + z1 * tA1.y)),
                    cvt_tf32(scl * (w2 * tB1.x + w1 * tB1.y)));
            }
        }
    }
}

// ---------------------------------------------------------------------------
// Flash attention, m32 warp tiles (R15 body — 60% of HMMA ceiling).
// ---------------------------------------------------------------------------
__global__ __launch_bounds__(128, 2) void flash_tf32(
    const float* __restrict__ Qg, const float* __restrict__ Kg,
    const float* __restrict__ Vg, const unsigned char* __restrict__ maskg,
    float* __restrict__ Out)
{
    extern __shared__ float sm[];
    float* Qf = sm;                 // 8448
    float* Kb = sm + 8448;          // 2 x 4224
    float* Vb = sm + 16896;         // 2 x 4224
    float* mk = sm + 25344;         // 2048

    const int tid = threadIdx.x, lane = tid & 31, warp = tid >> 5;
    const int g = lane >> 2, tig = lane & 3;
    const int sw4 = swsl(lane) << 2;
    const int q0 = blockIdx.x << 7;
    const int h  = blockIdx.y;
    const int b  = blockIdx.z;
    const size_t bh = (size_t)(b * NH + h) * SEQL * HD;

    const float* kbase = Kg + bh;
    const float* vbase = Vg + bh;

    const int cst = tid >> 4;
    const int csd = (tid & 15) << 2;

    int koff[4], voff[4];
#pragma unroll
    for (int u = 0; u < 4; u++) {
        koff[u] = kf_idx(csd + u, cst);
        voff[u] = vf_idx(vperm(cst), csd + u);
    }

    {
        const float* qp = Qg + bh + (size_t)q0 * HD;
#pragma unroll
        for (int jj = 0; jj < 16; jj++) {
            int c = tid + jj * 128;
            int row = c >> 4;
            int d4  = (c & 15) << 2;
            float4 qv = *(const float4*)&qp[(size_t)row * HD + d4];
            int w = row >> 4, m = row & 15;
#pragma unroll
            for (int u = 0; u < 4; u++)
                Qf[w * 1056 + qf_idx(m, d4 + u)] = ((const float*)&qv)[u];
        }
#pragma unroll
        for (int jj = 0; jj < 16; jj++) {
            int i = tid + jj * 128;
            mk[i] = maskg[b * SEQL + i] ? -1.0e9f : 0.0f;
        }
    }

    {
#pragma unroll
        for (int jj = 0; jj < 8; jj++) {
            int key = cst + jj * 8;
            float4 kv = *(const float4*)&kbase[(size_t)key * HD + csd];
            float4 vv = *(const float4*)&vbase[(size_t)key * HD + csd];
#pragma unroll
            for (int u = 0; u < 4; u++) {
                Kb[koff[u] + jj * 528] = ((const float*)&kv)[u];
                Vb[voff[u] + (jj >> 1) * 1056 + (jj & 1) * 2] = ((const float*)&vv)[u];
            }
        }
    }
    __syncthreads();

    float4 O[2][8];
#pragma unroll
    for (int mt = 0; mt < 2; mt++)
#pragma unroll
        for (int nt = 0; nt < 8; nt++) O[mt][nt] = make_float4(0.f,0.f,0.f,0.f);
    float l0 = 0.f, l1 = 0.f, l2 = 0.f, l3 = 0.f;

    for (int t = 0; t < SEQL / 64; t++) {
        const int buf = (t & 1) * 4224;
        const bool more = (t + 1 < SEQL / 64);

        float4 pk[8];
        if (more) {
#pragma unroll
            for (int jj = 0; jj < 8; jj++)
                pk[jj] = *(const float4*)&kbase[(size_t)((t+1)*64 + cst + jj*8) * HD + csd];
        }

        float4 S[2][8];
#pragma unroll
        for (int nt = 0; nt < 8; nt++) {
            float2 mv = *(const float2*)&mk[t * 64 + nt * 8 + tig * 2];
            S[0][nt] = make_float4(mv.x, mv.y, mv.x, mv.y);
            S[1][nt] = S[0][nt];
        }

        const float* Kf = Kb + buf;
        const float* Q0 = Qf + (2 * warp)     * 1056;
        const float* Q1 = Qf + (2 * warp + 1) * 1056;
#pragma unroll
        for (int k8p = 0; k8p < 4; k8p++) {
            float4 qa0 = *(const float4*)&Q0[(2 * k8p)     * 132 + sw4];
            float4 qb0 = *(const float4*)&Q0[(2 * k8p + 1) * 132 + sw4];
            float4 qa1 = *(const float4*)&Q1[(2 * k8p)     * 132 + sw4];
            float4 qb1 = *(const float4*)&Q1[(2 * k8p + 1) * 132 + sw4];
#pragma unroll
            for (int ng = 0; ng < 2; ng++) {
                float4 bq[4];
#pragma unroll
                for (int j = 0; j < 4; j++)
                    bq[j] = *(const float4*)&Kf[((ng * 4 + j) * 4 + k8p) * 132 + sw4];
#pragma unroll
                for (int j = 0; j < 4; j++) mma8(S[0][ng*4+j], qa0, bq[j].x, bq[j].y);
#pragma unroll
                for (int j = 0; j < 4; j++) mma8(S[1][ng*4+j], qa1, bq[j].x, bq[j].y);
#pragma unroll
                for (int j = 0; j < 4; j++) mma8(S[0][ng*4+j], qb0, bq[j].z, bq[j].w);
#pragma unroll
                for (int j = 0; j < 4; j++) mma8(S[1][ng*4+j], qb1, bq[j].z, bq[j].w);
            }
        }

        if (more) {
            float* Kn = Kb + (buf ^ 4224);
#pragma unroll
            for (int jj = 0; jj < 8; jj++)
#pragma unroll
                for (int u = 0; u < 4; u++)
                    Kn[koff[u] + jj * 528] = ((const float*)&pk[jj])[u];
        }

        float4 pv4[8];
        if (more) {
#pragma unroll
            for (int jj = 0; jj < 8; jj++)
                pv4[jj] = *(const float4*)&vbase[(size_t)((t+1)*64 + cst + jj*8) * HD + csd];
        }

#pragma unroll
        for (int nt = 0; nt < 8; nt++) {
            S[0][nt].x = ex2(S[0][nt].x); S[0][nt].y = ex2(S[0][nt].y);
            S[0][nt].z = ex2(S[0][nt].z); S[0][nt].w = ex2(S[0][nt].w);
            l0 += S[0][nt].x + S[0][nt].y;
            l1 += S[0][nt].z + S[0][nt].w;
            S[1][nt].x = ex2(S[1][nt].x); S[1][nt].y = ex2(S[1][nt].y);
            S[1][nt].z = ex2(S[1][nt].z); S[1][nt].w = ex2(S[1][nt].w);
            l2 += S[1][nt].x + S[1][nt].y;
            l3 += S[1][nt].z + S[1][nt].w;
        }

        const float* Vf = Vb + buf;
#pragma unroll
        for (int kp = 0; kp < 4; kp++) {
            float4 ape0 = apfrag(S[0][2*kp]);
            float4 apo0 = apfrag(S[0][2*kp+1]);
            float4 ape1 = apfrag(S[1][2*kp]);
            float4 apo1 = apfrag(S[1][2*kp+1]);
#pragma unroll
            for (int ng = 0; ng < 2; ng++) {
                float4 bv[4];
#pragma unroll
                for (int j = 0; j < 4; j++)
                    bv[j] = *(const float4*)&Vf[(kp * 8 + ng * 4 + j) * 132 + sw4];
#pragma unroll
                for (int j = 0; j < 4; j++) mma8(O[0][ng*4+j], ape0, bv[j].x, bv[j].y);
#pragma unroll
                for (int j = 0; j < 4; j++) mma8(O[1][ng*4+j], ape1, bv[j].x, bv[j].y);
#pragma unroll
                for (int j = 0; j < 4; j++) mma8(O[0][ng*4+j], apo0, bv[j].z, bv[j].w);
#pragma unroll
                for (int j = 0; j < 4; j++) mma8(O[1][ng*4+j], apo1, bv[j].z, bv[j].w);
            }
        }

        if (more) {
            float* Vn = Vb + (buf ^ 4224);
#pragma unroll
            for (int jj = 0; jj < 8; jj++)
#pragma unroll
                for (int u = 0; u < 4; u++)
                    Vn[voff[u] + (jj >> 1) * 1056 + (jj & 1) * 2] = ((const float*)&pv4[jj])[u];
        }
        __syncthreads();
    }

    l0 += __shfl_xor_sync(0xffffffffu, l0, 1);
    l0 += __shfl_xor_sync(0xffffffffu, l0, 2);
    l1 += __shfl_xor_sync(0xffffffffu, l1, 1);
    l1 += __shfl_xor_sync(0xffffffffu, l1, 2);
    l2 += __shfl_xor_sync(0xffffffffu, l2, 1);
    l2 += __shfl_xor_sync(0xffffffffu, l2, 2);
    l3 += __shfl_xor_sync(0xffffffffu, l3, 1);
    l3 += __shfl_xor_sync(0xffffffffu, l3, 2);
    float inv_[4] = {1.f / l0, 1.f / l1, 1.f / l2, 1.f / l3};
#pragma unroll
    for (int mt = 0; mt < 2; mt++) {
        int s0 = q0 + (2 * warp + mt) * 16 + g;
        float iv0 = inv_[2 * mt], iv1 = inv_[2 * mt + 1];
#pragma unroll
        for (int nt = 0; nt < 8; nt++) {
            int col = h * HD + nt * 8 + tig * 2;
            *(float2*)&Out[(size_t)(b * SEQL + s0) * EMB + col] =
                make_float2(O[mt][nt].x * iv0, O[mt][nt].y * iv0);
            *(float2*)&Out[(size_t)(b * SEQL + s0 + 8) * EMB + col] =
                make_float2(O[mt][nt].z * iv1, O[mt][nt].w * iv1);
        }
    }
}

// ---------------------------------------------------------------------------
extern "C" void kernel_launch(void* const* d_in, const int* in_sizes, int n_in,
                              void* d_out, int out_size)
{
    const float* x            = (const float*)d_in[0];
    const unsigned char* mask = (const unsigned char*)d_in[1];
    const float* Wqkv         = (const float*)d_in[2];
    const float* Wout         = (const float*)d_in[3];
    float* out = (float*)d_out;

    float *q, *k, *v, *attn;
    float2* rope;
    cudaGetSymbolAddress((void**)&q,    g_q);
    cudaGetSymbolAddress((void**)&k,    g_k);
    cudaGetSymbolAddress((void**)&v,    g_v);
    cudaGetSymbolAddress((void**)&attn, g_attn);
    cudaGetSymbolAddress((void**)&rope, g_rope);

    const int FLASH_SMEM = 27392 * 4;   // 109568 B
    cudaFuncSetAttribute(flash_tf32,
                         cudaFuncAttributeMaxDynamicSharedMemorySize, FLASH_SMEM);

    // rope table (deterministic, rebuilt every call)
    rope_init<<<(SEQL * 32) / 256, 256>>>(rope);

    // gemm1 fused with RoPE/split (table-based): writes q/k/v directly
    dim3 g1(NQKV / 128, M1 / 128);
    gemm_tf32<<<g1, 128>>>(x, Wqkv, nullptr, M1, NQKV, EMB, 1, q, k, v, rope);

    dim3 gf(SEQL / 128, NH, BATCH);
    flash_tf32<<<gf, 128, FLASH_SMEM>>>(q, k, v, mask, attn);

    dim3 g2(EMB / 128, M1 / 128);
    gemm_tf32<<<g2, 128>>>(attn, Wout, out, M1, EMB, EMB, 0,
                           nullptr, nullptr, nullptr, nullptr);
}